// round 2
// baseline (speedup 1.0000x reference)
#include <cuda_runtime.h>
#include <math.h>

#define B_ 2
#define L_ 4096
#define H_ 16
#define D_ 128
#define BLK 64
#define M_ 64
#define TOPK 6
#define NSPLIT 4
#define EPSV 1e-6f
#define SCALE 0.08838834764831845f   /* 1/sqrt(128) */

// ---------------- scratch (static device globals; no allocation) ----------------
__device__ float g_kfm [B_*L_*H_*D_];          // softmax feature of k, same layout as k
__device__ float g_pq  [B_*H_*M_*D_];
__device__ float g_pk  [B_*H_*M_*D_];
__device__ int   g_lut [B_*H_*M_*TOPK];
__device__ float g_kvp [NSPLIT*B_*H_*D_*D_];   // kvsum partials per split
__device__ float g_ksp [NSPLIT*B_*H_*D_];      // ksum partials
__device__ float g_ksum[B_*H_*D_];
__device__ float g_M2  [B_*H_*D_*D_];          // kvsum @ W^T per head

// ---------------- packed f32x2 helpers ----------------
__device__ __forceinline__ unsigned long long f2pack(float x, float y){
    unsigned long long r; asm("mov.b64 %0, {%1, %2};" : "=l"(r) : "f"(x), "f"(y)); return r;
}
__device__ __forceinline__ void f2unpack(unsigned long long v, float& x, float& y){
    asm("mov.b64 {%0, %1}, %2;" : "=f"(x), "=f"(y) : "l"(v));
}
__device__ __forceinline__ void f2fma(unsigned long long& a, unsigned long long b, unsigned long long c){
    asm("fma.rn.f32x2 %0, %1, %2, %0;" : "+l"(a) : "l"(b), "l"(c));
}
__device__ __forceinline__ void f2mul(unsigned long long& a, unsigned long long b){
    asm("mul.rn.f32x2 %0, %0, %1;" : "+l"(a) : "l"(b));
}

// ---------------- K1: k_fm = softmax(k, axis=D). one warp per row ----------------
__global__ void k_softmax_feat(const float* __restrict__ kin){
    int gid  = blockIdx.x * blockDim.x + threadIdx.x;
    int w    = gid >> 5;
    int lane = gid & 31;
    const float4* src = reinterpret_cast<const float4*>(kin) + (size_t)w * 32;
    float4 v = src[lane];
    float mx = fmaxf(fmaxf(v.x, v.y), fmaxf(v.z, v.w));
    #pragma unroll
    for (int o = 16; o; o >>= 1) mx = fmaxf(mx, __shfl_xor_sync(0xffffffffu, mx, o));
    float e0 = __expf(v.x - mx), e1 = __expf(v.y - mx);
    float e2 = __expf(v.z - mx), e3 = __expf(v.w - mx);
    float s = e0 + e1 + e2 + e3;
    #pragma unroll
    for (int o = 16; o; o >>= 1) s += __shfl_xor_sync(0xffffffffu, s, o);
    float inv = 1.f / s;
    reinterpret_cast<float4*>(g_kfm)[(size_t)w * 32 + lane] =
        make_float4(e0 * inv, e1 * inv, e2 * inv, e3 * inv);
}

// ---------------- K2: mean-pool q and k per 64-row block ----------------
__global__ void k_pool(const float* __restrict__ q, const float* __restrict__ kin){
    int bid = blockIdx.x;                 // b*H*M + h*M + m
    int m = bid % M_;
    int h = (bid / M_) % H_;
    int b = bid / (H_ * M_);
    int d = threadIdx.x;
    size_t base = ((size_t)(b * L_ + m * BLK) * H_ + h) * D_ + d;
    float sq = 0.f, sk = 0.f;
    #pragma unroll 4
    for (int i = 0; i < BLK; i++){
        sq += q  [base + (size_t)i * H_ * D_];
        sk += kin[base + (size_t)i * H_ * D_];
    }
    int o = ((b * H_ + h) * M_ + m) * D_ + d;
    g_pq[o] = sq * (1.f / BLK);
    g_pk[o] = sk * (1.f / BLK);
}

// ---------------- K3: kmean subtract, block scores, top-6 ----------------
__global__ void k_score_topk(){
    extern __shared__ float sh[];
    float* pq = sh;                 // 64*128
    float* pk = sh + 8192;          // 64*128
    float* sc = sh + 16384;         // 64*64
    float* km = sh + 20480;         // 128
    int bh = blockIdx.x;
    int t  = threadIdx.x;
    for (int i = t; i < 8192; i += 256){
        pq[i] = g_pq[bh * 8192 + i];
        pk[i] = g_pk[bh * 8192 + i];
    }
    __syncthreads();
    if (t < 128){
        float s = 0.f;
        for (int mm = 0; mm < 64; mm++) s += pk[mm * 128 + t];
        km[t] = s * (1.f / 64.f);
    }
    __syncthreads();
    for (int i = t; i < 8192; i += 256) pk[i] -= km[i & 127];
    __syncthreads();
    int tx = t & 15, ty = t >> 4;
    float acc[4][4];
    #pragma unroll
    for (int i = 0; i < 4; i++)
        #pragma unroll
        for (int j = 0; j < 4; j++) acc[i][j] = 0.f;
    for (int kk = 0; kk < 128; kk++){
        float a[4], bv[4];
        #pragma unroll
        for (int i = 0; i < 4; i++) a[i]  = pq[(ty * 4 + i) * 128 + kk];
        #pragma unroll
        for (int j = 0; j < 4; j++) bv[j] = pk[(tx * 4 + j) * 128 + kk];
        #pragma unroll
        for (int i = 0; i < 4; i++)
            #pragma unroll
            for (int j = 0; j < 4; j++) acc[i][j] += a[i] * bv[j];
    }
    #pragma unroll
    for (int i = 0; i < 4; i++)
        #pragma unroll
        for (int j = 0; j < 4; j++)
            sc[(ty * 4 + i) * 64 + tx * 4 + j] = acc[i][j];
    __syncthreads();
    if (t < 64){
        int sel[TOPK];
        for (int s = 0; s < TOPK; s++){
            float best = -3.4e38f; int bi = 0;
            for (int c = 0; c < 64; c++){
                float v = sc[t * 64 + c];
                if (v > best){ best = v; bi = c; }
            }
            sel[s] = bi;
            sc[t * 64 + bi] = -3.4e38f;
        }
        for (int s = 0; s < TOPK; s++) g_lut[(bh * 64 + t) * TOPK + s] = sel[s];
    }
}

// ---------------- K4: kvsum partials (split over L) + ksum partials ----------------
__global__ void __launch_bounds__(256) k_kvsum(const float* __restrict__ vin){
    __shared__ float kf_sh[16 * 132];
    __shared__ float v_sh [16 * 132];
    int bh = blockIdx.x >> 2;
    int split = blockIdx.x & 3;
    int b = bh >> 4, h = bh & 15;
    int t = threadIdx.x, tx = t & 15, ty = t >> 4;

    unsigned long long acc[8][4];
    #pragma unroll
    for (int i = 0; i < 8; i++)
        #pragma unroll
        for (int j = 0; j < 4; j++) acc[i][j] = 0ull;
    float kacc = 0.f;

    for (int chunk = 0; chunk < 64; chunk++){
        int lb = split * 1024 + chunk * 16;
        __syncthreads();
        #pragma unroll
        for (int jj = 0; jj < 2; jj++){
            int idx = t + jj * 256;
            int row = idx >> 5, c4 = idx & 31;
            size_t g = ((size_t)((b * L_ + lb + row) * H_ + h)) * 32 + c4;
            *reinterpret_cast<float4*>(&kf_sh[row * 132 + c4 * 4]) =
                reinterpret_cast<const float4*>(g_kfm)[g];
            *reinterpret_cast<float4*>(&v_sh[row * 132 + c4 * 4]) =
                reinterpret_cast<const float4*>(vin)[g];
        }
        __syncthreads();
        if (t < 128){
            #pragma unroll
            for (int kk = 0; kk < 16; kk++) kacc += kf_sh[kk * 132 + t];
        }
        for (int kk = 0; kk < 16; kk++){
            unsigned long long ad[8], bv[4];
            #pragma unroll
            for (int i = 0; i < 8; i++){
                float a = kf_sh[kk * 132 + ty * 8 + i];
                ad[i] = f2pack(a, a);
            }
            #pragma unroll
            for (int j = 0; j < 4; j++)
                bv[j] = *reinterpret_cast<const unsigned long long*>(
                            &v_sh[kk * 132 + (tx * 4 + j) * 2]);
            #pragma unroll
            for (int i = 0; i < 8; i++)
                #pragma unroll
                for (int j = 0; j < 4; j++) f2fma(acc[i][j], ad[i], bv[j]);
        }
    }
    float* dst = g_kvp + ((size_t)split * 32 + bh) * 16384;
    #pragma unroll
    for (int i = 0; i < 8; i++)
        #pragma unroll
        for (int j = 0; j < 4; j++)
            *reinterpret_cast<unsigned long long*>(
                &dst[(ty * 8 + i) * 128 + (tx * 4 + j) * 2]) = acc[i][j];
    if (t < 128) g_ksp[(split * 32 + bh) * 128 + t] = kacc;
}

// ---------------- K5: M2 = kvsum_total @ W^T ; finalize ksum ----------------
__global__ void k_m2(const float* __restrict__ W){
    extern __shared__ float sh[];
    float* kv = sh;             // 16384
    float* Wt = sh + 16384;     // 128*132 transposed
    int bh = blockIdx.x;
    int t  = threadIdx.x;
    for (int i = t; i < 16384; i += 256){
        float s = g_kvp[(size_t)(0 * 32 + bh) * 16384 + i]
                + g_kvp[(size_t)(1 * 32 + bh) * 16384 + i]
                + g_kvp[(size_t)(2 * 32 + bh) * 16384 + i]
                + g_kvp[(size_t)(3 * 32 + bh) * 16384 + i];
        kv[i] = s;
        int e = i >> 7, f = i & 127;
        Wt[f * 132 + e] = W[i];
    }
    if (t < 128){
        g_ksum[bh * 128 + t] = g_ksp[(0 * 32 + bh) * 128 + t]
                             + g_ksp[(1 * 32 + bh) * 128 + t]
                             + g_ksp[(2 * 32 + bh) * 128 + t]
                             + g_ksp[(3 * 32 + bh) * 128 + t];
    }
    __syncthreads();
    int tx = t & 15, ty = t >> 4;
    float acc[8][8];
    #pragma unroll
    for (int i = 0; i < 8; i++)
        #pragma unroll
        for (int j = 0; j < 8; j++) acc[i][j] = 0.f;
    for (int f = 0; f < 128; f++){
        float a[8], w[8];
        #pragma unroll
        for (int i = 0; i < 8; i++) a[i] = kv[(ty * 8 + i) * 128 + f];
        #pragma unroll
        for (int j = 0; j < 8; j++) w[j] = Wt[f * 132 + tx * 8 + j];
        #pragma unroll
        for (int i = 0; i < 8; i++)
            #pragma unroll
            for (int j = 0; j < 8; j++) acc[i][j] += a[i] * w[j];
    }
    float* dst = g_M2 + (size_t)bh * 16384;
    #pragma unroll
    for (int i = 0; i < 8; i++)
        #pragma unroll
        for (int j = 0; j < 8; j++)
            dst[(ty * 8 + i) * 128 + tx * 8 + j] = acc[i][j];
}

// ---------------- K6: fused block-sparse attention + linear branch + epilogue ----------------
__global__ void __launch_bounds__(256) k_main(
        const float* __restrict__ q, const float* __restrict__ kin,
        const float* __restrict__ vin, const float* __restrict__ bproj,
        float* __restrict__ out){
    extern __shared__ float sh[];
    float* Qs   = sh;            // 64*132
    float* Qf   = sh + 8448;     // 64*132
    float* Ks   = sh + 16896;    // 64*132
    float* Vs   = sh + 25344;    // 64*132
    float* M2s  = sh + 16896;    // union over Ks/Vs after attention (16384 floats)
    float* Ss   = sh + 33792;    // 64*68
    float* red  = sh + 38144;    // 256
    float* mrow = sh + 38400;    // 64
    float* lrow = sh + 38464;    // 64
    float* frow = sh + 38528;    // 64
    float* dden = sh + 38592;    // 64

    int bid = blockIdx.x;
    int m  = bid & 63;
    int bh = bid >> 6;
    int h  = bh & 15, b = bh >> 4;
    int t  = threadIdx.x, tx = t & 15, ty = t >> 4;

    // load Q block (64 rows x 128)
    #pragma unroll
    for (int jj = 0; jj < 8; jj++){
        int idx = t + jj * 256;
        int row = idx >> 5, c4 = idx & 31;
        size_t g = ((size_t)((b * L_ + m * BLK + row) * H_ + h)) * 32 + c4;
        *reinterpret_cast<float4*>(&Qs[row * 132 + c4 * 4]) =
            reinterpret_cast<const float4*>(q)[g];
    }
    if (t < 64){ mrow[t] = -3.4e38f; lrow[t] = 0.f; }
    __syncthreads();

    // q_fm (softmax over D) + den = eps + q_fm . ksum    (4 threads per row)
    {
        int r = t >> 2, p = t & 3;
        const float* qr = &Qs[r * 132 + p * 32];
        float*       fr = &Qf[r * 132 + p * 32];
        float mx = -3.4e38f;
        #pragma unroll 8
        for (int c = 0; c < 32; c++) mx = fmaxf(mx, qr[c]);
        red[r * 4 + p] = mx;
        __syncthreads();
        mx = fmaxf(fmaxf(red[r * 4], red[r * 4 + 1]), fmaxf(red[r * 4 + 2], red[r * 4 + 3]));
        float s = 0.f;
        #pragma unroll 8
        for (int c = 0; c < 32; c++){ float e = __expf(qr[c] - mx); fr[c] = e; s += e; }
        __syncthreads();
        red[r * 4 + p] = s;
        __syncthreads();
        s = red[r * 4] + red[r * 4 + 1] + red[r * 4 + 2] + red[r * 4 + 3];
        float inv = 1.f / s;
        const float* ks = g_ksum + bh * 128 + p * 32;
        float dd = 0.f;
        #pragma unroll 8
        for (int c = 0; c < 32; c++){ float v = fr[c] * inv; fr[c] = v; dd += v * ks[c]; }
        __syncthreads();
        red[r * 4 + p] = dd;
        __syncthreads();
        if (p == 0) dden[r] = EPSV + red[r * 4] + red[r * 4 + 1] + red[r * 4 + 2] + red[r * 4 + 3];
    }

    unsigned long long o2[4][4];
    #pragma unroll
    for (int i = 0; i < 4; i++)
        #pragma unroll
        for (int j = 0; j < 4; j++) o2[i][j] = 0ull;

    const int* lut = g_lut + (bh * 64 + m) * TOPK;

    for (int jb = 0; jb < TOPK; jb++){
        __syncthreads();                         // prior PV reads of Vs/Ss complete
        int kb = lut[jb];
        #pragma unroll
        for (int jj = 0; jj < 8; jj++){
            int idx = t + jj * 256;
            int row = idx >> 5, c4 = idx & 31;
            size_t g = ((size_t)((b * L_ + kb * BLK + row) * H_ + h)) * 32 + c4;
            *reinterpret_cast<float4*>(&Ks[row * 132 + c4 * 4]) =
                reinterpret_cast<const float4*>(kin)[g];
            *reinterpret_cast<float4*>(&Vs[row * 132 + c4 * 4]) =
                reinterpret_cast<const float4*>(vin)[g];
        }
        __syncthreads();

        // S = Q K^T (4x4 tile per thread, packed f32x2 over k)
        unsigned long long acc[4][4];
        #pragma unroll
        for (int i = 0; i < 4; i++)
            #pragma unroll
            for (int j = 0; j < 4; j++) acc[i][j] = 0ull;
        #pragma unroll 4
        for (int k2 = 0; k2 < 64; k2++){
            unsigned long long qa[4], kv[4];
            #pragma unroll
            for (int i = 0; i < 4; i++)
                qa[i] = *reinterpret_cast<const unsigned long long*>(
                            &Qs[(ty * 4 + i) * 132 + 2 * k2]);
            #pragma unroll
            for (int j = 0; j < 4; j++)
                kv[j] = *reinterpret_cast<const unsigned long long*>(
                            &Ks[(tx * 4 + j) * 132 + 2 * k2]);
            #pragma unroll
            for (int i = 0; i < 4; i++)
                #pragma unroll
                for (int j = 0; j < 4; j++) f2fma(acc[i][j], qa[i], kv[j]);
        }
        #pragma unroll
        for (int i = 0; i < 4; i++)
            #pragma unroll
            for (int j = 0; j < 4; j++){
                float x, y; f2unpack(acc[i][j], x, y);
                Ss[(ty * 4 + i) * 68 + tx * 4 + j] = (x + y) * SCALE;
            }
        __syncthreads();

        // online softmax row update (one thread per row)
        if (t < 64){
            float mold = mrow[t];
            float* sr = &Ss[t * 68];
            float mc = mold;
            #pragma unroll 8
            for (int c = 0; c < 64; c++) mc = fmaxf(mc, sr[c]);
            float f = __expf(mold - mc);
            float sum = 0.f;
            #pragma unroll 8
            for (int c = 0; c < 64; c++){ float pv = __expf(sr[c] - mc); sr[c] = pv; sum += pv; }
            mrow[t] = mc;
            lrow[t] = lrow[t] * f + sum;
            frow[t] = f;
        }
        __syncthreads();

        // rescale O, then O += P V
        #pragma unroll
        for (int i = 0; i < 4; i++){
            float f = frow[ty * 4 + i];
            unsigned long long fd = f2pack(f, f);
            #pragma unroll
            for (int j = 0; j < 4; j++) f2mul(o2[i][j], fd);
        }
        for (int c = 0; c < 64; c++){
            unsigned long long vv[4];
            #pragma unroll
            for (int j = 0; j < 4; j++)
                vv[j] = *reinterpret_cast<const unsigned long long*>(
                            &Vs[c * 132 + (tx * 4 + j) * 2]);
            #pragma unroll
            for (int i = 0; i < 4; i++){
                float pv = Ss[(ty * 4 + i) * 68 + c];
                unsigned long long pd = f2pack(pv, pv);
                #pragma unroll
                for (int j = 0; j < 4; j++) f2fma(o2[i][j], pd, vv[j]);
            }
        }
    }

    __syncthreads();
    // load per-head projected linear matrix M2 into smem (reuse Ks/Vs space)
    for (int i = t; i < 16384; i += 256) M2s[i] = g_M2[(size_t)bh * 16384 + i];
    __syncthreads();

    // linear branch: lacc[r][e] = sum_d q_fm[r][d] * M2[d][e]
    unsigned long long lacc[4][4];
    #pragma unroll
    for (int i = 0; i < 4; i++)
        #pragma unroll
        for (int j = 0; j < 4; j++) lacc[i][j] = 0ull;
    for (int d = 0; d < 128; d++){
        unsigned long long mv[4];
        #pragma unroll
        for (int j = 0; j < 4; j++)
            mv[j] = *reinterpret_cast<const unsigned long long*>(
                        &M2s[d * 128 + (tx * 4 + j) * 2]);
        #pragma unroll
        for (int i = 0; i < 4; i++){
            float qv = Qf[(ty * 4 + i) * 132 + d];
            unsigned long long qd = f2pack(qv, qv);
            #pragma unroll
            for (int j = 0; j < 4; j++) f2fma(lacc[i][j], qd, mv[j]);
        }
    }

    // epilogue: out = O/l + lin/den + b
    #pragma unroll
    for (int i = 0; i < 4; i++){
        int r = ty * 4 + i;
        float invl = 1.f / lrow[r];
        float invd = 1.f / dden[r];
        size_t ob = ((size_t)((b * L_ + m * BLK + r) * H_ + h)) * 128;
        #pragma unroll
        for (int j = 0; j < 4; j++){
            float ox, oy, lx, ly;
            f2unpack(o2[i][j], ox, oy);
            f2unpack(lacc[i][j], lx, ly);
            int e = (tx * 4 + j) * 2;
            float2 bp = *reinterpret_cast<const float2*>(&bproj[e]);
            float2 res = make_float2(ox * invl + lx * invd + bp.x,
                                     oy * invl + ly * invd + bp.y);
            *reinterpret_cast<float2*>(&out[ob + e]) = res;
        }
    }
}

// ---------------- launch ----------------
extern "C" void kernel_launch(void* const* d_in, const int* in_sizes, int n_in,
                              void* d_out, int out_size){
    (void)in_sizes; (void)n_in; (void)out_size;
    const float* q  = (const float*)d_in[0];
    const float* k  = (const float*)d_in[1];
    const float* v  = (const float*)d_in[2];
    const float* W  = (const float*)d_in[3];
    const float* bp = (const float*)d_in[4];
    float* out = (float*)d_out;

    cudaFuncSetAttribute(k_score_topk, cudaFuncAttributeMaxDynamicSharedMemorySize, 82432);
    cudaFuncSetAttribute(k_m2,         cudaFuncAttributeMaxDynamicSharedMemorySize, 133120);
    cudaFuncSetAttribute(k_main,       cudaFuncAttributeMaxDynamicSharedMemorySize, 154624);

    k_softmax_feat<<<16384, 256>>>(k);         // k_fm
    k_pool        <<<2048, 128>>>(q, k);       // pooled q / k
    k_score_topk  <<<32, 256, 82432>>>();      // routing lut
    k_kvsum       <<<128, 256>>>(v);           // kvsum partials + ksum partials
    k_m2          <<<32, 256, 133120>>>(W);    // M2 = kvsum @ W^T, ksum finalize
    k_main        <<<2048, 256, 154624>>>(q, k, v, bp, out);
}

// round 4
// speedup vs baseline: 2.1436x; 2.1436x over previous
#include <cuda_runtime.h>
#include <math.h>

#define B_ 2
#define L_ 4096
#define H_ 16
#define D_ 128
#define BLK 64
#define M_ 64
#define TOPK 6
#define NSPLIT 16
#define EPSV 1e-6f
#define SCALE 0.08838834764831845f   /* 1/sqrt(128) */

// ---------------- scratch (static device globals; no allocation) ----------------
__device__ float g_kfm [B_*L_*H_*D_];
__device__ float g_pq  [B_*H_*M_*D_];
__device__ float g_pk  [B_*H_*M_*D_];
__device__ int   g_lut [B_*H_*M_*TOPK];
__device__ float g_kvp [NSPLIT*B_*H_*D_*D_];
__device__ float g_ksp [NSPLIT*B_*H_*D_];
__device__ float g_ksum[B_*H_*D_];
__device__ float g_M2  [B_*H_*D_*D_];

// ---------------- helpers ----------------
__device__ __forceinline__ float tf32f(float x){
    unsigned u; asm("cvt.rna.tf32.f32 %0, %1;" : "=r"(u) : "f"(x));
    return __uint_as_float(u);
}
__device__ __forceinline__ void mma_tf32(float d[4],
        unsigned a0, unsigned a1, unsigned a2, unsigned a3,
        unsigned b0, unsigned b1){
    asm("mma.sync.aligned.m16n8k8.row.col.f32.tf32.tf32.f32 "
        "{%0,%1,%2,%3}, {%4,%5,%6,%7}, {%8,%9}, {%0,%1,%2,%3};"
        : "+f"(d[0]), "+f"(d[1]), "+f"(d[2]), "+f"(d[3])
        : "r"(a0), "r"(a1), "r"(a2), "r"(a3), "r"(b0), "r"(b1));
}
__device__ __forceinline__ unsigned long long f2pack(float x, float y){
    unsigned long long r; asm("mov.b64 %0, {%1, %2};" : "=l"(r) : "f"(x), "f"(y)); return r;
}
__device__ __forceinline__ void f2fma(unsigned long long& a, unsigned long long b, unsigned long long c){
    asm("fma.rn.f32x2 %0, %1, %2, %0;" : "+l"(a) : "l"(b), "l"(c));
}

// ---------------- K1: k_fm = softmax(k, axis=D). one warp per row ----------------
__global__ void k_softmax_feat(const float* __restrict__ kin){
    int gid  = blockIdx.x * blockDim.x + threadIdx.x;
    int w    = gid >> 5;
    int lane = gid & 31;
    const float4* src = reinterpret_cast<const float4*>(kin) + (size_t)w * 32;
    float4 v = src[lane];
    float mx = fmaxf(fmaxf(v.x, v.y), fmaxf(v.z, v.w));
    #pragma unroll
    for (int o = 16; o; o >>= 1) mx = fmaxf(mx, __shfl_xor_sync(0xffffffffu, mx, o));
    float e0 = __expf(v.x - mx), e1 = __expf(v.y - mx);
    float e2 = __expf(v.z - mx), e3 = __expf(v.w - mx);
    float s = e0 + e1 + e2 + e3;
    #pragma unroll
    for (int o = 16; o; o >>= 1) s += __shfl_xor_sync(0xffffffffu, s, o);
    float inv = 1.f / s;
    reinterpret_cast<float4*>(g_kfm)[(size_t)w * 32 + lane] =
        make_float4(e0 * inv, e1 * inv, e2 * inv, e3 * inv);
}

// ---------------- K2: mean-pool q and k per 64-row block ----------------
__global__ void k_pool(const float* __restrict__ q, const float* __restrict__ kin){
    int bid = blockIdx.x;
    int m = bid % M_;
    int h = (bid / M_) % H_;
    int b = bid / (H_ * M_);
    int d = threadIdx.x;
    size_t base = ((size_t)(b * L_ + m * BLK) * H_ + h) * D_ + d;
    float sq = 0.f, sk = 0.f;
    #pragma unroll 4
    for (int i = 0; i < BLK; i++){
        sq += q  [base + (size_t)i * H_ * D_];
        sk += kin[base + (size_t)i * H_ * D_];
    }
    int o = ((b * H_ + h) * M_ + m) * D_ + d;
    g_pq[o] = sq * (1.f / BLK);
    g_pk[o] = sk * (1.f / BLK);
}

// ---------------- K3: kmean subtract, block scores, top-6 (exact fp32) ----------------
__global__ void k_score_topk(){
    extern __shared__ float sh[];
    float* pq = sh;
    float* pk = sh + 8192;
    float* sc = sh + 16384;
    float* km = sh + 20480;
    int bh = blockIdx.x;
    int t  = threadIdx.x;
    for (int i = t; i < 8192; i += 256){
        pq[i] = g_pq[bh * 8192 + i];
        pk[i] = g_pk[bh * 8192 + i];
    }
    __syncthreads();
    if (t < 128){
        float s = 0.f;
        for (int mm = 0; mm < 64; mm++) s += pk[mm * 128 + t];
        km[t] = s * (1.f / 64.f);
    }
    __syncthreads();
    for (int i = t; i < 8192; i += 256) pk[i] -= km[i & 127];
    __syncthreads();
    int tx = t & 15, ty = t >> 4;
    float acc[4][4];
    #pragma unroll
    for (int i = 0; i < 4; i++)
        #pragma unroll
        for (int j = 0; j < 4; j++) acc[i][j] = 0.f;
    for (int kk = 0; kk < 128; kk++){
        float a[4], bv[4];
        #pragma unroll
        for (int i = 0; i < 4; i++) a[i]  = pq[(ty * 4 + i) * 128 + kk];
        #pragma unroll
        for (int j = 0; j < 4; j++) bv[j] = pk[(tx * 4 + j) * 128 + kk];
        #pragma unroll
        for (int i = 0; i < 4; i++)
            #pragma unroll
            for (int j = 0; j < 4; j++) acc[i][j] += a[i] * bv[j];
    }
    #pragma unroll
    for (int i = 0; i < 4; i++)
        #pragma unroll
        for (int j = 0; j < 4; j++)
            sc[(ty * 4 + i) * 64 + tx * 4 + j] = acc[i][j];
    __syncthreads();
    if (t < 64){
        int sel[TOPK];
        for (int s = 0; s < TOPK; s++){
            float best = -3.4e38f; int bi = 0;
            for (int c = 0; c < 64; c++){
                float v = sc[t * 64 + c];
                if (v > best){ best = v; bi = c; }
            }
            sel[s] = bi;
            sc[t * 64 + bi] = -3.4e38f;
        }
        for (int s = 0; s < TOPK; s++) g_lut[(bh * 64 + t) * TOPK + s] = sel[s];
    }
}

// ---------------- K4: kvsum partials (16 splits over L) + ksum partials ----------------
__global__ void __launch_bounds__(256) k_kvsum(const float* __restrict__ vin){
    __shared__ float kf_sh[16 * 132];
    __shared__ float v_sh [16 * 132];
    int bh = blockIdx.x >> 4;
    int split = blockIdx.x & 15;
    int b = bh >> 4, h = bh & 15;
    int t = threadIdx.x, tx = t & 15, ty = t >> 4;

    unsigned long long acc[8][4];
    #pragma unroll
    for (int i = 0; i < 8; i++)
        #pragma unroll
        for (int j = 0; j < 4; j++) acc[i][j] = 0ull;
    float kacc = 0.f;

    for (int chunk = 0; chunk < 16; chunk++){
        int lb = split * 256 + chunk * 16;
        __syncthreads();
        #pragma unroll
        for (int jj = 0; jj < 2; jj++){
            int idx = t + jj * 256;
            int row = idx >> 5, c4 = idx & 31;
            size_t g = ((size_t)((b * L_ + lb + row) * H_ + h)) * 32 + c4;
            *reinterpret_cast<float4*>(&kf_sh[row * 132 + c4 * 4]) =
                reinterpret_cast<const float4*>(g_kfm)[g];
            *reinterpret_cast<float4*>(&v_sh[row * 132 + c4 * 4]) =
                reinterpret_cast<const float4*>(vin)[g];
        }
        __syncthreads();
        if (t < 128){
            #pragma unroll
            for (int kk = 0; kk < 16; kk++) kacc += kf_sh[kk * 132 + t];
        }
        for (int kk = 0; kk < 16; kk++){
            unsigned long long ad[8], bv[4];
            #pragma unroll
            for (int i = 0; i < 8; i++){
                float a = kf_sh[kk * 132 + ty * 8 + i];
                ad[i] = f2pack(a, a);
            }
            #pragma unroll
            for (int j = 0; j < 4; j++)
                bv[j] = *reinterpret_cast<const unsigned long long*>(
                            &v_sh[kk * 132 + (tx * 4 + j) * 2]);
            #pragma unroll
            for (int i = 0; i < 8; i++)
                #pragma unroll
                for (int j = 0; j < 4; j++) f2fma(acc[i][j], ad[i], bv[j]);
        }
    }
    float* dst = g_kvp + ((size_t)split * 32 + bh) * 16384;
    #pragma unroll
    for (int i = 0; i < 8; i++)
        #pragma unroll
        for (int j = 0; j < 4; j++)
            *reinterpret_cast<unsigned long long*>(
                &dst[(ty * 8 + i) * 128 + (tx * 4 + j) * 2]) = acc[i][j];
    if (t < 128) g_ksp[(split * 32 + bh) * 128 + t] = kacc;
}

// ---------------- K5: M2 = kvsum_total @ W^T ; finalize ksum ----------------
__global__ void k_m2(const float* __restrict__ W){
    extern __shared__ float sh[];
    float* kv = sh;             // 16384
    float* Wt = sh + 16384;     // 128*132
    int bh = blockIdx.x;
    int t  = threadIdx.x;
    for (int i = t; i < 16384; i += 256){
        float s = 0.f;
        #pragma unroll
        for (int sp = 0; sp < NSPLIT; sp++)
            s += g_kvp[((size_t)sp * 32 + bh) * 16384 + i];
        kv[i] = s;
        int e = i >> 7, f = i & 127;
        Wt[f * 132 + e] = W[i];
    }
    if (t < 128){
        float s = 0.f;
        #pragma unroll
        for (int sp = 0; sp < NSPLIT; sp++)
            s += g_ksp[(sp * 32 + bh) * 128 + t];
        g_ksum[bh * 128 + t] = s;
    }
    __syncthreads();
    int tx = t & 15, ty = t >> 4;
    float acc[8][8];
    #pragma unroll
    for (int i = 0; i < 8; i++)
        #pragma unroll
        for (int j = 0; j < 8; j++) acc[i][j] = 0.f;
    for (int f = 0; f < 128; f++){
        float a[8], w[8];
        #pragma unroll
        for (int i = 0; i < 8; i++) a[i] = kv[(ty * 8 + i) * 128 + f];
        #pragma unroll
        for (int j = 0; j < 8; j++) w[j] = Wt[f * 132 + tx * 8 + j];
        #pragma unroll
        for (int i = 0; i < 8; i++)
            #pragma unroll
            for (int j = 0; j < 8; j++) acc[i][j] += a[i] * w[j];
    }
    float* dst = g_M2 + (size_t)bh * 16384;
    #pragma unroll
    for (int i = 0; i < 8; i++)
        #pragma unroll
        for (int j = 0; j < 8; j++)
            dst[(ty * 8 + i) * 128 + tx * 8 + j] = acc[i][j];
}

// ---------------- K6: linear branch, writes out = (q_fm @ M2)/den + bias ----------------
__global__ void __launch_bounds__(256) k_linear(
        const float* __restrict__ q, const float* __restrict__ bproj,
        float* __restrict__ out){
    extern __shared__ float sh[];
    float* Qs   = sh;            // 64*132 (raw Q, then q_fm as tf32)
    float* M2s  = sh + 8448;     // 128*132 (tf32)
    float* dden = sh + 25344;    // 64

    int bid = blockIdx.x;
    int m  = bid & 63;
    int bh = bid >> 6;
    int h  = bh & 15, b = bh >> 4;
    int t  = threadIdx.x;
    int w = t >> 5, lane = t & 31;
    int g = lane >> 2, tg = lane & 3;
    int wr = w >> 1, wc = w & 1;

    // load Q block raw
    #pragma unroll
    for (int jj = 0; jj < 8; jj++){
        int idx = t + jj * 256;
        int row = idx >> 5, c4 = idx & 31;
        size_t gi = ((size_t)((b * L_ + m * BLK + row) * H_ + h)) * 32 + c4;
        *reinterpret_cast<float4*>(&Qs[row * 132 + c4 * 4]) =
            reinterpret_cast<const float4*>(q)[gi];
    }
    // load M2 (converted to tf32)
    for (int i = t; i < 16384; i += 256){
        int r = i >> 7, c = i & 127;
        M2s[r * 132 + c] = tf32f(g_M2[(size_t)bh * 16384 + i]);
    }
    __syncthreads();

    // q_fm softmax over D + den (4 threads per row, 32 cols each)
    {
        int row = t >> 2, part = t & 3;
        float* sr = &Qs[row * 132 + part * 32];
        float mx = -3.4e38f;
        #pragma unroll 8
        for (int c = 0; c < 32; c++) mx = fmaxf(mx, sr[c]);
        mx = fmaxf(mx, __shfl_xor_sync(0xffffffffu, mx, 1));
        mx = fmaxf(mx, __shfl_xor_sync(0xffffffffu, mx, 2));
        float s = 0.f;
        float ebuf[32];
        #pragma unroll 8
        for (int c = 0; c < 32; c++){ float e = __expf(sr[c] - mx); ebuf[c] = e; s += e; }
        s += __shfl_xor_sync(0xffffffffu, s, 1);
        s += __shfl_xor_sync(0xffffffffu, s, 2);
        float inv = 1.f / s;
        const float* ks = g_ksum + bh * 128 + part * 32;
        float dd = 0.f;
        #pragma unroll 8
        for (int c = 0; c < 32; c++){
            float v = ebuf[c] * inv;
            dd += v * ks[c];
            sr[c] = tf32f(v);
        }
        dd += __shfl_xor_sync(0xffffffffu, dd, 1);
        dd += __shfl_xor_sync(0xffffffffu, dd, 2);
        if (part == 0) dden[row] = EPSV + dd;
    }
    __syncthreads();

    // GEMM: Lacc[r][e] = sum_d q_fm[r][d] * M2[d][e], warp = 16 rows x 64 cols
    float Lacc[8][4];
    #pragma unroll
    for (int i = 0; i < 8; i++)
        #pragma unroll
        for (int j = 0; j < 4; j++) Lacc[i][j] = 0.f;
    #pragma unroll 4
    for (int k8 = 0; k8 < 16; k8++){
        int kc = k8 * 8 + tg;
        unsigned a0 = __float_as_uint(Qs[(wr * 16 + g    ) * 132 + kc]);
        unsigned a1 = __float_as_uint(Qs[(wr * 16 + g + 8) * 132 + kc]);
        unsigned a2 = __float_as_uint(Qs[(wr * 16 + g    ) * 132 + kc + 4]);
        unsigned a3 = __float_as_uint(Qs[(wr * 16 + g + 8) * 132 + kc + 4]);
        #pragma unroll
        for (int nt = 0; nt < 8; nt++){
            int n0 = wc * 64 + nt * 8 + g;
            unsigned b0 = __float_as_uint(M2s[(kc    ) * 132 + n0]);
            unsigned b1 = __float_as_uint(M2s[(kc + 4) * 132 + n0]);
            mma_tf32(Lacc[nt], a0, a1, a2, a3, b0, b1);
        }
    }

    // epilogue: out = Lacc/den + bias
    float id0 = 1.f / dden[wr * 16 + g];
    float id1 = 1.f / dden[wr * 16 + g + 8];
    int r0 = m * BLK + wr * 16 + g;
    #pragma unroll
    for (int nt = 0; nt < 8; nt++){
        int col = wc * 64 + nt * 8 + 2 * tg;
        float2 bp = *reinterpret_cast<const float2*>(&bproj[col]);
        float2 v0 = make_float2(Lacc[nt][0] * id0 + bp.x, Lacc[nt][1] * id0 + bp.y);
        float2 v1 = make_float2(Lacc[nt][2] * id1 + bp.x, Lacc[nt][3] * id1 + bp.y);
        *reinterpret_cast<float2*>(&out[((size_t)((b * L_ + r0    ) * H_ + h)) * 128 + col]) = v0;
        *reinterpret_cast<float2*>(&out[((size_t)((b * L_ + r0 + 8) * H_ + h)) * 128 + col]) = v1;
    }
}

// ---------------- K7: block-sparse attention (tf32 mma), accumulates into out ----------------
__global__ void __launch_bounds__(256) k_main(
        const float* __restrict__ q, const float* __restrict__ kin,
        const float* __restrict__ vin, float* __restrict__ out){
    extern __shared__ float sh[];
    float* Qs   = sh;            // 64*132 (tf32, pre-scaled)
    float* Ks   = sh + 8448;     // 64*132 (tf32)
    float* Vs   = sh + 16896;    // 64*132 (tf32)
    float* Ss   = sh + 25344;    // 64*68
    float* mrow = sh + 29696;    // 64
    float* lrow = sh + 29760;    // 64
    float* frow = sh + 29824;    // 64

    int bid = blockIdx.x;
    int m  = bid & 63;
    int bh = bid >> 6;
    int h  = bh & 15, b = bh >> 4;
    int t  = threadIdx.x;
    int w = t >> 5, lane = t & 31;
    int g = lane >> 2, tg = lane & 3;
    int wr = w >> 1, wc = w & 1;

    // load Q block (scaled + tf32)
    #pragma unroll
    for (int jj = 0; jj < 8; jj++){
        int idx = t + jj * 256;
        int row = idx >> 5, c4 = idx & 31;
        size_t gi = ((size_t)((b * L_ + m * BLK + row) * H_ + h)) * 32 + c4;
        float4 v = reinterpret_cast<const float4*>(q)[gi];
        v.x = tf32f(v.x * SCALE); v.y = tf32f(v.y * SCALE);
        v.z = tf32f(v.z * SCALE); v.w = tf32f(v.w * SCALE);
        *reinterpret_cast<float4*>(&Qs[row * 132 + c4 * 4]) = v;
    }
    if (t < 64){ mrow[t] = -3.4e38f; lrow[t] = 0.f; }

    float Oacc[8][4];
    #pragma unroll
    for (int i = 0; i < 8; i++)
        #pragma unroll
        for (int j = 0; j < 4; j++) Oacc[i][j] = 0.f;

    const int* lut = g_lut + (bh * 64 + m) * TOPK;

    for (int jb = 0; jb < TOPK; jb++){
        __syncthreads();                 // prior PV done reading Vs/Ss
        int kb = lut[jb];
        #pragma unroll
        for (int jj = 0; jj < 8; jj++){
            int idx = t + jj * 256;
            int row = idx >> 5, c4 = idx & 31;
            size_t gi = ((size_t)((b * L_ + kb * BLK + row) * H_ + h)) * 32 + c4;
            float4 kv = reinterpret_cast<const float4*>(kin)[gi];
            float4 vv = reinterpret_cast<const float4*>(vin)[gi];
            kv.x = tf32f(kv.x); kv.y = tf32f(kv.y); kv.z = tf32f(kv.z); kv.w = tf32f(kv.w);
            vv.x = tf32f(vv.x); vv.y = tf32f(vv.y); vv.z = tf32f(vv.z); vv.w = tf32f(vv.w);
            *reinterpret_cast<float4*>(&Ks[row * 132 + c4 * 4]) = kv;
            *reinterpret_cast<float4*>(&Vs[row * 132 + c4 * 4]) = vv;
        }
        __syncthreads();

        // S = Q K^T  : warp tile 16x32, k = 128
        float Sacc[4][4];
        #pragma unroll
        for (int i = 0; i < 4; i++)
            #pragma unroll
            for (int j = 0; j < 4; j++) Sacc[i][j] = 0.f;
        #pragma unroll 4
        for (int k8 = 0; k8 < 16; k8++){
            int kc = k8 * 8 + tg;
            unsigned a0 = __float_as_uint(Qs[(wr * 16 + g    ) * 132 + kc]);
            unsigned a1 = __float_as_uint(Qs[(wr * 16 + g + 8) * 132 + kc]);
            unsigned a2 = __float_as_uint(Qs[(wr * 16 + g    ) * 132 + kc + 4]);
            unsigned a3 = __float_as_uint(Qs[(wr * 16 + g + 8) * 132 + kc + 4]);
            #pragma unroll
            for (int nt = 0; nt < 4; nt++){
                int n0 = wc * 32 + nt * 8 + g;
                unsigned b0 = __float_as_uint(Ks[n0 * 132 + kc]);
                unsigned b1 = __float_as_uint(Ks[n0 * 132 + kc + 4]);
                mma_tf32(Sacc[nt], a0, a1, a2, a3, b0, b1);
            }
        }
        #pragma unroll
        for (int nt = 0; nt < 4; nt++){
            int col = wc * 32 + nt * 8 + 2 * tg;
            *reinterpret_cast<float2*>(&Ss[(wr * 16 + g    ) * 68 + col]) =
                make_float2(Sacc[nt][0], Sacc[nt][1]);
            *reinterpret_cast<float2*>(&Ss[(wr * 16 + g + 8) * 68 + col]) =
                make_float2(Sacc[nt][2], Sacc[nt][3]);
        }
        __syncthreads();

        // online softmax: 4 threads per row, 16 cols each
        {
            int row = t >> 2, qd = t & 3;
            float mold = mrow[row];
            float* sr = &Ss[row * 68 + qd * 16];
            float mc = mold;
            #pragma unroll 4
            for (int c = 0; c < 16; c++) mc = fmaxf(mc, sr[c]);
            mc = fmaxf(mc, __shfl_xor_sync(0xffffffffu, mc, 1));
            mc = fmaxf(mc, __shfl_xor_sync(0xffffffffu, mc, 2));
            float sum = 0.f;
            #pragma unroll 4
            for (int c = 0; c < 16; c++){
                float e = __expf(sr[c] - mc);
                sum += e;
                sr[c] = tf32f(e);
            }
            sum += __shfl_xor_sync(0xffffffffu, sum, 1);
            sum += __shfl_xor_sync(0xffffffffu, sum, 2);
            if (qd == 0){
                float f = __expf(mold - mc);
                frow[row] = f;
                mrow[row] = mc;
                lrow[row] = lrow[row] * f + sum;
            }
        }
        __syncthreads();

        // rescale O, then O += P V  : warp tile 16 rows x 64 cols, k = 64
        float f0 = frow[wr * 16 + g];
        float f1 = frow[wr * 16 + g + 8];
        #pragma unroll
        for (int nt = 0; nt < 8; nt++){
            Oacc[nt][0] *= f0; Oacc[nt][1] *= f0;
            Oacc[nt][2] *= f1; Oacc[nt][3] *= f1;
        }
        #pragma unroll 2
        for (int k8 = 0; k8 < 8; k8++){
            int kc = k8 * 8 + tg;
            unsigned a0 = __float_as_uint(Ss[(wr * 16 + g    ) * 68 + kc]);
            unsigned a1 = __float_as_uint(Ss[(wr * 16 + g + 8) * 68 + kc]);
            unsigned a2 = __float_as_uint(Ss[(wr * 16 + g    ) * 68 + kc + 4]);
            unsigned a3 = __float_as_uint(Ss[(wr * 16 + g + 8) * 68 + kc + 4]);
            #pragma unroll
            for (int nt = 0; nt < 8; nt++){
                int n0 = wc * 64 + nt * 8 + g;
                unsigned b0 = __float_as_uint(Vs[(kc    ) * 132 + n0]);
                unsigned b1 = __float_as_uint(Vs[(kc + 4) * 132 + n0]);
                mma_tf32(Oacc[nt], a0, a1, a2, a3, b0, b1);
            }
        }
    }
    __syncthreads();

    // epilogue: out += O / l   (out already holds linear branch)
    float il0 = 1.f / lrow[wr * 16 + g];
    float il1 = 1.f / lrow[wr * 16 + g + 8];
    int r0 = m * BLK + wr * 16 + g;
    #pragma unroll
    for (int nt = 0; nt < 8; nt++){
        int col = wc * 64 + nt * 8 + 2 * tg;
        float2* p0 = reinterpret_cast<float2*>(&out[((size_t)((b * L_ + r0    ) * H_ + h)) * 128 + col]);
        float2* p1 = reinterpret_cast<float2*>(&out[((size_t)((b * L_ + r0 + 8) * H_ + h)) * 128 + col]);
        float2 o0 = *p0, o1 = *p1;
        o0.x += Oacc[nt][0] * il0; o0.y += Oacc[nt][1] * il0;
        o1.x += Oacc[nt][2] * il1; o1.y += Oacc[nt][3] * il1;
        *p0 = o0; *p1 = o1;
    }
}

// ---------------- launch ----------------
extern "C" void kernel_launch(void* const* d_in, const int* in_sizes, int n_in,
                              void* d_out, int out_size){
    (void)in_sizes; (void)n_in; (void)out_size;
    const float* q  = (const float*)d_in[0];
    const float* k  = (const float*)d_in[1];
    const float* v  = (const float*)d_in[2];
    const float* W  = (const float*)d_in[3];
    const float* bp = (const float*)d_in[4];
    float* out = (float*)d_out;

    cudaFuncSetAttribute(k_score_topk, cudaFuncAttributeMaxDynamicSharedMemorySize, 82432);
    cudaFuncSetAttribute(k_m2,         cudaFuncAttributeMaxDynamicSharedMemorySize, 133120);
    cudaFuncSetAttribute(k_linear,     cudaFuncAttributeMaxDynamicSharedMemorySize, 101632);
    cudaFuncSetAttribute(k_main,       cudaFuncAttributeMaxDynamicSharedMemorySize, 119552);

    k_softmax_feat<<<16384, 256>>>(k);
    k_pool        <<<2048, 128>>>(q, k);
    k_score_topk  <<<32, 256, 82432>>>();
    k_kvsum       <<<512, 256>>>(v);
    k_m2          <<<32, 256, 133120>>>(W);
    k_linear      <<<2048, 256, 101632>>>(q, bp, out);
    k_main        <<<2048, 256, 119552>>>(q, k, v, out);
}